// round 6
// baseline (speedup 1.0000x reference)
#include <cuda_runtime.h>

// TemporalGCN fused persistent kernel, round 2.
// Pipeline per (b,t) tile (using associativity (A@x)@W^T == A@(x@W^T)):
//   H0 = x @ W0^T        [24(pad) x 128], K=192
//   g1 = relu(A @ H0 + b0)
//   H1 = g1 @ W1^T       K=128
//   g2 = relu(A @ H1 + b1);  out = mean_c g2
//
// Weights k-major in SMEM (conflict-free LDS.128 on h), broadcast operands
// (x, g1, A) stored duplicated {v,v} so fma.rn.f32x2 needs no pack MOVs.

#define CC 22
#define CP 24          // padded C
#define FF 192
#define HH 128
#define NTILES (32 * 512)

#define THREADS 384    // 32 h-groups (4 h each) x 12 c-groups (2 c each)
#define GRID 148

// SMEM float offsets
#define OFF_W0 0                         // [192][128] k-major       24576
#define OFF_W1 (OFF_W0 + FF * HH)        // [128][128] k-major       16384
#define OFF_R1 (OFF_W1 + HH * HH)        // xsd[24][384] / g1d[24][256] / red[12][128]
#define R1_SZ  (CP * 2 * FF)             // 9216
#define OFF_AS (OFF_R1 + R1_SZ)          // Asd[24][48] duplicated   1152
#define OFF_H  (OFF_AS + CP * 48)        // H0/H1 [24][128]          3072
#define OFF_B0 (OFF_H + CP * HH)
#define OFF_B1 (OFF_B0 + HH)
#define SMEM_FLOATS (OFF_B1 + HH)        // 54656
#define SMEM_BYTES (SMEM_FLOATS * 4)     // 218624

__device__ __forceinline__ float2 ffma2(float2 a, float2 b, float2 c) {
    float2 d;
    asm("fma.rn.f32x2 %0, %1, %2, %3;"
        : "=l"(*reinterpret_cast<unsigned long long*>(&d))
        : "l"(*reinterpret_cast<const unsigned long long*>(&a)),
          "l"(*reinterpret_cast<const unsigned long long*>(&b)),
          "l"(*reinterpret_cast<const unsigned long long*>(&c)));
    return d;
}

// One register-blocked GEMM: out[c0..c0+1][hb..hb+3] = xd @ Wk
// xd: duplicated rows, pitch 2*K.  Wk: k-major [K][128].
template<int K>
__device__ __forceinline__ void gemm_2x4(const float* __restrict__ Wk,
                                         const float* __restrict__ xr0,
                                         const float* __restrict__ xr1,
                                         int hb, float* __restrict__ Hs,
                                         int c0)
{
    float2 a00 = make_float2(0.f, 0.f), a01 = a00, a10 = a00, a11 = a00;
    #pragma unroll 8
    for (int kb = 0; kb < K / 4; kb++) {
        const float* wk = Wk + (kb * 4) * HH + hb;
        float4 w[4];
        #pragma unroll
        for (int kk = 0; kk < 4; kk++)
            w[kk] = *reinterpret_cast<const float4*>(wk + kk * HH);
        #pragma unroll
        for (int kk = 0; kk < 4; kk++) {
            float2 wlo = make_float2(w[kk].x, w[kk].y);
            float2 whi = make_float2(w[kk].z, w[kk].w);
            float2 xa = *reinterpret_cast<const float2*>(xr0 + 2 * (kb * 4 + kk));
            float2 xb = *reinterpret_cast<const float2*>(xr1 + 2 * (kb * 4 + kk));
            a00 = ffma2(xa, wlo, a00);
            a01 = ffma2(xa, whi, a01);
            a10 = ffma2(xb, wlo, a10);
            a11 = ffma2(xb, whi, a11);
        }
    }
    *reinterpret_cast<float4*>(Hs + c0 * HH + hb) =
        make_float4(a00.x, a00.y, a01.x, a01.y);
    *reinterpret_cast<float4*>(Hs + (c0 + 1) * HH + hb) =
        make_float4(a10.x, a10.y, a11.x, a11.y);
}

extern "C" __global__ void __launch_bounds__(THREADS, 1)
tgcn_kernel(const float* __restrict__ x, const float* __restrict__ A,
            const float* __restrict__ W0, const float* __restrict__ b0,
            const float* __restrict__ W1, const float* __restrict__ b1,
            float* __restrict__ out)
{
    extern __shared__ float smem[];
    float* Ws0 = smem + OFF_W0;
    float* Ws1 = smem + OFF_W1;
    float* R1  = smem + OFF_R1;   // xsd pitch 384 / g1d pitch 256 / red pitch 128
    float* Asd = smem + OFF_AS;   // pitch 48, duplicated
    float* Hs  = smem + OFF_H;    // pitch 128
    float* b0s = smem + OFF_B0;
    float* b1s = smem + OFF_B1;

    const int tid = threadIdx.x;

    // ---- one-time init: transpose weights to k-major, biases, Asd pad rows ----
    for (int i = tid; i < HH * FF; i += THREADS) {
        int h = i / FF, k = i - h * FF;
        Ws0[k * HH + h] = W0[i];
    }
    for (int i = tid; i < HH * HH; i += THREADS) {
        int h = i >> 7, k = i & 127;
        Ws1[k * HH + h] = W1[i];
    }
    if (tid < HH) { b0s[tid] = b0[tid]; b1s[tid] = b1[tid]; }
    for (int i = tid; i < 2 * 48; i += THREADS) Asd[CC * 48 + i] = 0.f;  // pad rows 22,23
    __syncthreads();

    const int hg = tid & 31;
    const int cg = tid >> 5;          // == warp id; warp-uniform
    const int hb = hg * 4;
    const int c0 = cg * 2;

    for (int tile = blockIdx.x; tile < NTILES; tile += gridDim.x) {
        // ---- load x (duplicated) and A (duplicated) ----
        {
            const float4* xg = reinterpret_cast<const float4*>(x + (size_t)tile * (CC * FF));
            #pragma unroll
            for (int it = 0; it < 3; it++) {
                int i = tid + it * THREADS;
                if (i < CC * FF / 4) {
                    float4 v = xg[i];
                    int c = i / 48;
                    int k = 4 * (i - c * 48);
                    float* dst = R1 + c * (2 * FF) + 2 * k;
                    *reinterpret_cast<float4*>(dst)     = make_float4(v.x, v.x, v.y, v.y);
                    *reinterpret_cast<float4*>(dst + 4) = make_float4(v.z, v.z, v.w, v.w);
                }
            }
            const float* Ag = A + (size_t)tile * (CC * CC);
            #pragma unroll
            for (int it = 0; it < 2; it++) {
                int i = tid + it * THREADS;
                if (i < CC * CC) {
                    float a = Ag[i];
                    int c = i / 22, j = i - 22 * c;
                    *reinterpret_cast<float2*>(Asd + c * 48 + 2 * j) = make_float2(a, a);
                }
            }
        }
        __syncthreads();

        // ---- GEMM1: H0 = xd @ Ws0  (K=192) ----
        gemm_2x4<FF>(Ws0, R1 + c0 * (2 * FF), R1 + (c0 + 1) * (2 * FF), hb, Hs, c0);
        __syncthreads();

        // ---- mix1: g1 = relu(A @ H0 + b0), store duplicated into R1 (pitch 256) ----
        {
            float2 m00 = make_float2(0.f, 0.f), m01 = m00, m10 = m00, m11 = m00;
            #pragma unroll
            for (int j = 0; j < CC; j++) {
                float4 hv = *reinterpret_cast<const float4*>(Hs + j * HH + hb);
                float2 A0 = *reinterpret_cast<const float2*>(Asd + c0 * 48 + 2 * j);
                float2 A1 = *reinterpret_cast<const float2*>(Asd + (c0 + 1) * 48 + 2 * j);
                float2 hlo = make_float2(hv.x, hv.y);
                float2 hhi = make_float2(hv.z, hv.w);
                m00 = ffma2(A0, hlo, m00);
                m01 = ffma2(A0, hhi, m01);
                m10 = ffma2(A1, hlo, m10);
                m11 = ffma2(A1, hhi, m11);
            }
            float4 bb = *reinterpret_cast<const float4*>(b0s + hb);
            float v0 = fmaxf(m00.x + bb.x, 0.f), v1 = fmaxf(m00.y + bb.y, 0.f);
            float v2 = fmaxf(m01.x + bb.z, 0.f), v3 = fmaxf(m01.y + bb.w, 0.f);
            float u0 = fmaxf(m10.x + bb.x, 0.f), u1 = fmaxf(m10.y + bb.y, 0.f);
            float u2 = fmaxf(m11.x + bb.z, 0.f), u3 = fmaxf(m11.y + bb.w, 0.f);
            float* g0 = R1 + c0 * (2 * HH) + 2 * hb;
            float* g1r = R1 + (c0 + 1) * (2 * HH) + 2 * hb;
            *reinterpret_cast<float4*>(g0)      = make_float4(v0, v0, v1, v1);
            *reinterpret_cast<float4*>(g0 + 4)  = make_float4(v2, v2, v3, v3);
            *reinterpret_cast<float4*>(g1r)     = make_float4(u0, u0, u1, u1);
            *reinterpret_cast<float4*>(g1r + 4) = make_float4(u2, u2, u3, u3);
        }
        __syncthreads();

        // ---- GEMM2: H1 = g1d @ Ws1  (K=128), H1 aliases H0 ----
        gemm_2x4<HH>(Ws1, R1 + c0 * (2 * HH), R1 + (c0 + 1) * (2 * HH), hb, Hs, c0);
        __syncthreads();

        // ---- mix2 + relu + partial mean: red[cg][h] = sum over this thread's c ----
        {
            float2 m00 = make_float2(0.f, 0.f), m01 = m00, m10 = m00, m11 = m00;
            #pragma unroll
            for (int j = 0; j < CC; j++) {
                float4 hv = *reinterpret_cast<const float4*>(Hs + j * HH + hb);
                float2 A0 = *reinterpret_cast<const float2*>(Asd + c0 * 48 + 2 * j);
                float2 A1 = *reinterpret_cast<const float2*>(Asd + (c0 + 1) * 48 + 2 * j);
                float2 hlo = make_float2(hv.x, hv.y);
                float2 hhi = make_float2(hv.z, hv.w);
                m00 = ffma2(A0, hlo, m00);
                m01 = ffma2(A0, hhi, m01);
                m10 = ffma2(A1, hlo, m10);
                m11 = ffma2(A1, hhi, m11);
            }
            float4 bb = *reinterpret_cast<const float4*>(b1s + hb);
            float4 s;
            if (cg < 11) {
                s.x = fmaxf(m00.x + bb.x, 0.f) + fmaxf(m10.x + bb.x, 0.f);
                s.y = fmaxf(m00.y + bb.y, 0.f) + fmaxf(m10.y + bb.y, 0.f);
                s.z = fmaxf(m01.x + bb.z, 0.f) + fmaxf(m11.x + bb.z, 0.f);
                s.w = fmaxf(m01.y + bb.w, 0.f) + fmaxf(m11.y + bb.w, 0.f);
            } else {
                s = make_float4(0.f, 0.f, 0.f, 0.f);
            }
            *reinterpret_cast<float4*>(R1 + cg * HH + hb) = s;   // red region
        }
        __syncthreads();

        // ---- final reduce over 11 c-group partials -> out ----
        if (tid < HH) {
            float s = 0.f;
            #pragma unroll
            for (int g = 0; g < 11; g++) s += R1[g * HH + tid];
            out[(size_t)tile * HH + tid] = s * (1.f / (float)CC);
        }
        __syncthreads();   // protect R1/Asd before next tile's load
    }
}

extern "C" void kernel_launch(void* const* d_in, const int* in_sizes, int n_in,
                              void* d_out, int out_size)
{
    const float* x  = (const float*)d_in[0];
    const float* A  = (const float*)d_in[1];
    const float* W0 = (const float*)d_in[2];
    const float* b0 = (const float*)d_in[3];
    const float* W1 = (const float*)d_in[4];
    const float* b1 = (const float*)d_in[5];
    float* out = (float*)d_out;

    cudaFuncSetAttribute(tgcn_kernel, cudaFuncAttributeMaxDynamicSharedMemorySize, SMEM_BYTES);
    tgcn_kernel<<<GRID, THREADS, SMEM_BYTES>>>(x, A, W0, b0, W1, b1, out);
}

// round 12
// speedup vs baseline: 2.2501x; 2.2501x over previous
#include <cuda_runtime.h>
#include <cstdint>

// TemporalGCN on tcgen05 TF32 (TS mode). Supertile = 5 tiles = 110 rows (M=128 pad).
//  x -> tf32 hi/lo -> TMEM; MMA1 D = x_hi@W0^T + x_lo@W0^T (K=192)
//  LDTM -> smem H; mix1 g1 = relu(A@H + b0) on CUDA cores; g1 hi/lo -> TMEM
//  MMA2 (K=128); LDTM -> H; mix2 + relu + per-tile mean -> out.
//
// tcgen05 is arch-SPECIFIC: body gated on __CUDA_ARCH_FEAT_SM103_ALL so the
// plain compute_103 PTX pass and host pass never see tcgen05 or device symbols.

#if defined(__CUDA_ARCH_FEAT_SM103_ALL) || defined(__CUDA_ARCH_FEAT_SM100_ALL)
#define TC_OK 1
#else
#define TC_OK 0
#endif

#define CC 22
#define FF 192
#define HH 128
#define NTILES 16384
#define TPS 5
#define RPS (TPS * CC)                 // 110
#define NSUPER ((NTILES + TPS - 1) / TPS)   // 3277
#define THREADS 256
#define GRID 148
#define XROWS (NTILES * CC)            // 360448

// SMEM float offsets
#define OFF_W0 0                        // [128][192] tf32, SW128-blocked (1024B-aligned)
#define OFF_W1 (OFF_W0 + HH * FF)       // byte 98304, 1024B-aligned
#define OFF_H  (OFF_W1 + HH * HH)       // H buffer [110][128], XOR-swizzled float4 slots
#define OFF_A  (OFF_H + RPS * HH)       // A tiles [5][22][22]
#define OFF_B0 (OFF_A + TPS * CC * CC)
#define OFF_B1 (OFF_B0 + HH)
#define OFF_CTRL (OFF_B1 + HH)          // [0..1] mbar, [2] tmem ptr
#define SMEM_FLOATS (OFF_CTRL + 4)
#define SMEM_BYTES (SMEM_FLOATS * 4)    // 230880

// TMEM columns (512 alloc)
#define T_XHI 0
#define T_XLO 192
#define T_GHI 0
#define T_GLO 128
#define T_D   384
#define TMEM_COLS 512

// idesc: dtype F32(1)@4, atype TF32(2)@7, btype TF32(2)@10, N/8@17, M/16@24
#define IDESC_TF32 ((1u << 4) | (2u << 7) | (2u << 10) | ((HH / 8) << 17) | ((HH / 16) << 24))

// SW128 K-major descriptor base: layout=SW128(2), version=1, SBO=64, LBO=1.
// Preprocessor constant (NOT a __device__ symbol: host registration stub).
#define DESC_BASE ((2ULL << 61) | (1ULL << 46) | (64ULL << 32) | (1ULL << 16))

// ---------------- helpers (arch-neutral) ----------------
__device__ __forceinline__ uint32_t smem_u32(const void* p) {
    uint32_t a;
    asm("{ .reg .u64 t; cvta.to.shared.u64 t, %1; cvt.u32.u64 %0, t; }" : "=r"(a) : "l"(p));
    return a;
}
__device__ __forceinline__ uint32_t f2tf32(float x) {
    uint32_t u; asm("cvt.rna.tf32.f32 %0, %1;" : "=r"(u) : "f"(x)); return u;
}
__device__ __forceinline__ float2 ffma2(float2 a, float2 b, float2 c) {
    float2 d;
    asm("fma.rn.f32x2 %0, %1, %2, %3;"
        : "=l"(*reinterpret_cast<unsigned long long*>(&d))
        : "l"(*reinterpret_cast<const unsigned long long*>(&a)),
          "l"(*reinterpret_cast<const unsigned long long*>(&b)),
          "l"(*reinterpret_cast<const unsigned long long*>(&c)));
    return d;
}

#if TC_OK
__device__ __forceinline__ uint32_t elect1() {
    uint32_t p;
    asm volatile("{ .reg .pred p; elect.sync _|p, 0xFFFFFFFF; selp.b32 %0, 1, 0, p; }" : "=r"(p));
    return p;
}

#define TC_ALLOC(sa, n)   asm volatile("tcgen05.alloc.cta_group::1.sync.aligned.shared::cta.b32 [%0], %1;" :: "r"(sa), "r"((uint32_t)(n)) : "memory")
#define TC_DEALLOC(t, n)  asm volatile("tcgen05.dealloc.cta_group::1.sync.aligned.b32 %0, %1;" :: "r"(t), "r"((uint32_t)(n)))
#define TC_WAIT_ST()      asm volatile("tcgen05.wait::st.sync.aligned;" ::: "memory")
#define TC_WAIT_LD()      asm volatile("tcgen05.wait::ld.sync.aligned;" ::: "memory")
#define TC_FENCE_BEFORE() asm volatile("tcgen05.fence::before_thread_sync;" ::: "memory")
#define TC_FENCE_AFTER()  asm volatile("tcgen05.fence::after_thread_sync;" ::: "memory")
#define TC_COMMIT(mb)     asm volatile("tcgen05.commit.cta_group::1.mbarrier::arrive::one.shared::cluster.b64 [%0];" :: "r"(mb) : "memory")
#define MB_INIT(a, c)     asm volatile("mbarrier.init.shared.b64 [%0], %1;" :: "r"(a), "r"((uint32_t)(c)) : "memory")

#define MB_WAIT_PARITY(mbar, par) do {                                          \
    uint32_t _m = (mbar), _p = (par), _d;                                       \
    asm volatile("{ .reg .pred p; mbarrier.try_wait.parity.acquire.cta.shared::cta.b64 p, [%1], %2; selp.b32 %0, 1, 0, p; }" \
        : "=r"(_d) : "r"(_m), "r"(_p) : "memory");                              \
    if (!_d) {                                                                  \
        asm volatile("{ .reg .pred P1; WL_%=: mbarrier.try_wait.parity.acquire.cta.shared::cta.b64 P1, [%0], %1, 0x989680; @P1 bra.uni WD_%=; bra.uni WL_%=; WD_%=: }" \
            :: "r"(_m), "r"(_p) : "memory");                                    \
    }                                                                           \
} while (0)

#define STTM_X32(ta, r) \
    asm volatile("tcgen05.st.sync.aligned.32x32b.x32.b32 [%0], " \
        "{%1,%2,%3,%4,%5,%6,%7,%8,%9,%10,%11,%12,%13,%14,%15,%16," \
        "%17,%18,%19,%20,%21,%22,%23,%24,%25,%26,%27,%28,%29,%30,%31,%32};" \
        :: "r"(ta), \
        "r"((r)[0]),"r"((r)[1]),"r"((r)[2]),"r"((r)[3]),"r"((r)[4]),"r"((r)[5]),"r"((r)[6]),"r"((r)[7]), \
        "r"((r)[8]),"r"((r)[9]),"r"((r)[10]),"r"((r)[11]),"r"((r)[12]),"r"((r)[13]),"r"((r)[14]),"r"((r)[15]), \
        "r"((r)[16]),"r"((r)[17]),"r"((r)[18]),"r"((r)[19]),"r"((r)[20]),"r"((r)[21]),"r"((r)[22]),"r"((r)[23]), \
        "r"((r)[24]),"r"((r)[25]),"r"((r)[26]),"r"((r)[27]),"r"((r)[28]),"r"((r)[29]),"r"((r)[30]),"r"((r)[31]) \
        : "memory")

#define LDTM_X32(r, ta) \
    asm volatile("tcgen05.ld.sync.aligned.32x32b.x32.b32 " \
        "{%0,%1,%2,%3,%4,%5,%6,%7,%8,%9,%10,%11,%12,%13,%14,%15," \
        "%16,%17,%18,%19,%20,%21,%22,%23,%24,%25,%26,%27,%28,%29,%30,%31}, [%32];" \
        : "=r"((r)[0]),"=r"((r)[1]),"=r"((r)[2]),"=r"((r)[3]),"=r"((r)[4]),"=r"((r)[5]),"=r"((r)[6]),"=r"((r)[7]), \
          "=r"((r)[8]),"=r"((r)[9]),"=r"((r)[10]),"=r"((r)[11]),"=r"((r)[12]),"=r"((r)[13]),"=r"((r)[14]),"=r"((r)[15]), \
          "=r"((r)[16]),"=r"((r)[17]),"=r"((r)[18]),"=r"((r)[19]),"=r"((r)[20]),"=r"((r)[21]),"=r"((r)[22]),"=r"((r)[23]), \
          "=r"((r)[24]),"=r"((r)[25]),"=r"((r)[26]),"=r"((r)[27]),"=r"((r)[28]),"=r"((r)[29]),"=r"((r)[30]),"=r"((r)[31]) \
        : "r"(ta))

__device__ __forceinline__ void mma_tf32(uint32_t d, uint32_t a, uint64_t desc, uint32_t en) {
    asm volatile("{\n\t.reg .pred p;\n\tsetp.ne.u32 p, %4, 0;\n\t"
        "tcgen05.mma.cta_group::1.kind::tf32 [%0], [%1], %2, %3, p;\n\t}"
        :: "r"(d), "r"(a), "l"(desc), "r"((uint32_t)IDESC_TF32), "r"(en) : "memory");
}
#endif  // TC_OK

// Blocked SW128 smem offset for weight element (n,k): atoms of 8 n-rows x 32 k
__device__ __forceinline__ uint32_t wblk_off(int n, int k) {
    uint32_t off = (uint32_t)((n >> 3) + (k >> 5) * 16) * 1024u
                 + (uint32_t)(n & 7) * 128u + (uint32_t)(k & 31) * 4u;
    return off ^ ((off >> 3) & 0x70);
}

extern "C" __global__ void __launch_bounds__(THREADS, 1)
tgcn_tc_kernel(const float* __restrict__ x, const float* __restrict__ A,
               const float* __restrict__ W0, const float* __restrict__ b0,
               const float* __restrict__ W1, const float* __restrict__ b1,
               float* __restrict__ out)
{
#if TC_OK
    extern __shared__ float smemf[];
    uint32_t* smemu = reinterpret_cast<uint32_t*>(smemf);
    const int tid = threadIdx.x;
    const int w = tid >> 5, l = tid & 31;
    const int lw = w & 3;                 // TMEM subpartition (wid % 4)
    const int half = w >> 2;              // column-half ownership
    const int r = 32 * lw + l;            // M-row staged by this thread
    const uint32_t wofs = (uint32_t)lw << 21;

    const uint32_t mbar = smem_u32(smemf + OFF_CTRL);

    // ---- one-time: TMEM alloc, weights (tf32-rounded, SW128-blocked), biases ----
    if (w == 0) TC_ALLOC(smem_u32(smemf + OFF_CTRL + 2), TMEM_COLS);
    if (tid == 0) MB_INIT(mbar, 1);

    for (int i = tid; i < HH * FF; i += THREADS) {
        int h = i / FF, k = i - h * FF;
        smemu[OFF_W0 + (wblk_off(h, k) >> 2)] = f2tf32(W0[i]);
    }
    for (int i = tid; i < HH * HH; i += THREADS) {
        int h = i >> 7, k = i & 127;
        smemu[OFF_W1 + (wblk_off(h, k) >> 2)] = f2tf32(W1[i]);
    }
    if (tid < HH) { smemf[OFF_B0 + tid] = b0[tid]; smemf[OFF_B1 + tid] = b1[tid]; }
    __syncthreads();

    const uint32_t tb = smemu[OFF_CTRL + 2];
    const uint64_t d0 = DESC_BASE | ((uint64_t)(smem_u32(smemf + OFF_W0) >> 4) & 0x3FFF);
    const uint64_t d1 = DESC_BASE | ((uint64_t)(smem_u32(smemf + OFF_W1) >> 4) & 0x3FFF);
    uint32_t par = 0;

    const float4 bias0 = *reinterpret_cast<const float4*>(smemf + OFF_B0 + 4 * l);
    const float4 bias1 = *reinterpret_cast<const float4*>(smemf + OFF_B1 + 4 * l);

    for (int s = blockIdx.x; s < NSUPER; s += gridDim.x) {
        // ---- stage x -> tf32 hi/lo -> TMEM; stage A -> SMEM ----
        {
            long grow = (long)RPS * s + r;
            if (grow >= XROWS) grow = XROWS - 1;
            const float* xr = x + grow * FF;
            #pragma unroll
            for (int ch = 0; ch < 3; ch++) {
                int c0 = half * 96 + ch * 32;
                uint32_t hi[32], lo[32];
                #pragma unroll
                for (int u = 0; u < 8; u++) {
                    float4 v = *reinterpret_cast<const float4*>(xr + c0 + 4 * u);
                    hi[4*u+0] = f2tf32(v.x); lo[4*u+0] = f2tf32(v.x - __uint_as_float(hi[4*u+0]));
                    hi[4*u+1] = f2tf32(v.y); lo[4*u+1] = f2tf32(v.y - __uint_as_float(hi[4*u+1]));
                    hi[4*u+2] = f2tf32(v.z); lo[4*u+2] = f2tf32(v.z - __uint_as_float(hi[4*u+2]));
                    hi[4*u+3] = f2tf32(v.w); lo[4*u+3] = f2tf32(v.w - __uint_as_float(hi[4*u+3]));
                }
                STTM_X32(tb + T_XHI + c0 + wofs, hi);
                STTM_X32(tb + T_XLO + c0 + wofs, lo);
            }
            TC_WAIT_ST();
            for (int i = tid; i < TPS * CC * CC; i += THREADS) {
                int tt = i / (CC * CC);
                long g = (long)s * TPS + tt;
                if (g > NTILES - 1) g = NTILES - 1;
                smemf[OFF_A + i] = A[g * (CC * CC) + (i - tt * (CC * CC))];
            }
        }
        TC_FENCE_BEFORE();
        __syncthreads();

        // ---- MMA1: D = x_hi @ W0^T + x_lo @ W0^T  (K=192) ----
        if (w == 0) {
            TC_FENCE_AFTER();
            if (elect1()) {
                #pragma unroll
                for (int k = 0; k < 24; k++)
                    mma_tf32(tb + T_D, tb + T_XHI + 8 * k,
                             d0 + (uint64_t)((k >> 2) * 1024 + (k & 3) * 2), k > 0);
                #pragma unroll
                for (int k = 0; k < 24; k++)
                    mma_tf32(tb + T_D, tb + T_XLO + 8 * k,
                             d0 + (uint64_t)((k >> 2) * 1024 + (k & 3) * 2), 1);
                TC_COMMIT(mbar);
            }
        }
        MB_WAIT_PARITY(mbar, par); par ^= 1;
        TC_FENCE_AFTER();

        // ---- LDTM D -> SMEM H (xor-swizzled float4 slots) ----
        #pragma unroll
        for (int ch = 0; ch < 2; ch++) {
            int c0 = half * 64 + 32 * ch;
            uint32_t dr[32];
            LDTM_X32(dr, tb + T_D + c0);
            TC_WAIT_LD();
            if (r < RPS) {
                #pragma unroll
                for (int u = 0; u < 8; u++) {
                    uint32_t bs = ((uint32_t)(c0 >> 2) + u) ^ (uint32_t)(r & 31);
                    *reinterpret_cast<float4*>(smemf + OFF_H + r * HH + 4 * bs) =
                        make_float4(__uint_as_float(dr[4*u]), __uint_as_float(dr[4*u+1]),
                                    __uint_as_float(dr[4*u+2]), __uint_as_float(dr[4*u+3]));
                }
            }
        }
        __syncthreads();

        // ---- mix1: g1 = relu(A @ H + b0) ----
        float4 g1v[14];
        #pragma unroll
        for (int i = 0; i < 14; i++) {
            int c = w + 8 * i;
            if (c < RPS) {
                int tt = c / CC, ci = c - CC * tt;
                const float* Arow = smemf + OFF_A + tt * (CC * CC) + ci * CC;
                float2 a01 = make_float2(bias0.x, bias0.y);
                float2 a23 = make_float2(bias0.z, bias0.w);
                #pragma unroll 11
                for (int j = 0; j < CC; j++) {
                    int jj = tt * CC + j;
                    float av = Arow[j];
                    float2 av2 = make_float2(av, av);
                    const float4 hv = *reinterpret_cast<const float4*>(
                        smemf + OFF_H + jj * HH + 4 * ((uint32_t)l ^ (uint32_t)(jj & 31)));
                    a01 = ffma2(av2, make_float2(hv.x, hv.y), a01);
                    a23 = ffma2(av2, make_float2(hv.z, hv.w), a23);
                }
                g1v[i] = make_float4(fmaxf(a01.x, 0.f), fmaxf(a01.y, 0.f),
                                     fmaxf(a23.x, 0.f), fmaxf(a23.y, 0.f));
            }
        }
        __syncthreads();
        #pragma unroll
        for (int i = 0; i < 14; i++) {
            int c = w + 8 * i;
            if (c < RPS)
                *reinterpret_cast<float4*>(smemf + OFF_H + c * HH +
                    4 * ((uint32_t)l ^ (uint32_t)(c & 31))) = g1v[i];
        }
        __syncthreads();

        // ---- g1 -> tf32 hi/lo -> TMEM ----
        {
            int rc = (r < RPS) ? r : (RPS - 1);
            #pragma unroll
            for (int ch = 0; ch < 2; ch++) {
                int c0 = half * 64 + 32 * ch;
                uint32_t hi[32], lo[32];
                #pragma unroll
                for (int u = 0; u < 8; u++) {
                    uint32_t bs = ((uint32_t)(c0 >> 2) + u) ^ (uint32_t)(rc & 31);
                    float4 v = *reinterpret_cast<const float4*>(smemf + OFF_H + rc * HH + 4 * bs);
                    hi[4*u+0] = f2tf32(v.x); lo[4*u+0] = f2tf32(v.x - __uint_as_float(hi[4*u+0]));
                    hi[4*u+1] = f2tf32(v.y); lo[4*u+1] = f2tf32(v.y - __uint_as_float(hi[4*u+1]));
                    hi[4*u+2] = f2tf32(v.z); lo[4*u+2] = f2tf32(v.z - __uint_as_float(hi[4*u+2]));
                    hi[4*u+3] = f2tf32(v.w); lo[4*u+3] = f2tf32(v.w - __uint_as_float(hi[4*u+3]));
                }
                STTM_X32(tb + T_GHI + c0 + wofs, hi);
                STTM_X32(tb + T_GLO + c0 + wofs, lo);
            }
            TC_WAIT_ST();
        }
        TC_FENCE_BEFORE();
        __syncthreads();

        // ---- MMA2: D = g1_hi @ W1^T + g1_lo @ W1^T  (K=128) ----
        if (w == 0) {
            TC_FENCE_AFTER();
            if (elect1()) {
                #pragma unroll
                for (int k = 0; k < 16; k++)
                    mma_tf32(tb + T_D, tb + T_GHI + 8 * k,
                             d1 + (uint64_t)((k >> 2) * 1024 + (k & 3) * 2), k > 0);
                #pragma unroll
                for (int k = 0; k < 16; k++)
                    mma_tf32(tb + T_D, tb + T_GLO + 8 * k,
                             d1 + (uint64_t)((k >> 2) * 1024 + (k & 3) * 2), 1);
                TC_COMMIT(mbar);
            }
        }
        MB_WAIT_PARITY(mbar, par); par ^= 1;
        TC_FENCE_AFTER();

        // ---- LDTM D -> SMEM H ----
        #pragma unroll
        for (int ch = 0; ch < 2; ch++) {
            int c0 = half * 64 + 32 * ch;
            uint32_t dr[32];
            LDTM_X32(dr, tb + T_D + c0);
            TC_WAIT_LD();
            if (r < RPS) {
                #pragma unroll
                for (int u = 0; u < 8; u++) {
                    uint32_t bs = ((uint32_t)(c0 >> 2) + u) ^ (uint32_t)(r & 31);
                    *reinterpret_cast<float4*>(smemf + OFF_H + r * HH + 4 * bs) =
                        make_float4(__uint_as_float(dr[4*u]), __uint_as_float(dr[4*u+1]),
                                    __uint_as_float(dr[4*u+2]), __uint_as_float(dr[4*u+3]));
                }
            }
        }
        __syncthreads();

        // ---- mix2 + relu + per-tile accumulation ----
        float4 s0 = make_float4(0,0,0,0), s1 = s0, s2 = s0, s3 = s0, s4 = s0;
        #pragma unroll
        for (int i = 0; i < 14; i++) {
            int c = w + 8 * i;
            if (c < RPS) {
                int tt = c / CC, ci = c - CC * tt;
                const float* Arow = smemf + OFF_A + tt * (CC * CC) + ci * CC;
                float2 a01 = make_float2(bias1.x, bias1.y);
                float2 a23 = make_float2(bias1.z, bias1.w);
                #pragma unroll 11
                for (int j = 0; j < CC; j++) {
                    int jj = tt * CC + j;
                    float av = Arow[j];
                    float2 av2 = make_float2(av, av);
                    const float4 hv = *reinterpret_cast<const float4*>(
                        smemf + OFF_H + jj * HH + 4 * ((uint32_t)l ^ (uint32_t)(jj & 31)));
                    a01 = ffma2(av2, make_float2(hv.x, hv.y), a01);
                    a23 = ffma2(av2, make_float2(hv.z, hv.w), a23);
                }
                float4 gv = make_float4(fmaxf(a01.x, 0.f), fmaxf(a01.y, 0.f),
                                        fmaxf(a23.x, 0.f), fmaxf(a23.y, 0.f));
                if      (tt == 0) { s0.x += gv.x; s0.y += gv.y; s0.z += gv.z; s0.w += gv.w; }
                else if (tt == 1) { s1.x += gv.x; s1.y += gv.y; s1.z += gv.z; s1.w += gv.w; }
                else if (tt == 2) { s2.x += gv.x; s2.y += gv.y; s2.z += gv.z; s2.w += gv.w; }
                else if (tt == 3) { s3.x += gv.x; s3.y += gv.y; s3.z += gv.z; s3.w += gv.w; }
                else              { s4.x += gv.x; s4.y += gv.y; s4.z += gv.z; s4.w += gv.w; }
            }
        }
        __syncthreads();   // H reads done; reuse H region for reduction partials
        *reinterpret_cast<float4*>(smemf + OFF_H + (w * TPS + 0) * HH + 4 * l) = s0;
        *reinterpret_cast<float4*>(smemf + OFF_H + (w * TPS + 1) * HH + 4 * l) = s1;
        *reinterpret_cast<float4*>(smemf + OFF_H + (w * TPS + 2) * HH + 4 * l) = s2;
        *reinterpret_cast<float4*>(smemf + OFF_H + (w * TPS + 3) * HH + 4 * l) = s3;
        *reinterpret_cast<float4*>(smemf + OFF_H + (w * TPS + 4) * HH + 4 * l) = s4;
        __syncthreads();

        // ---- reduce over 8 warps -> out ----
        for (int idx = tid; idx < TPS * HH; idx += THREADS) {
            int tt = idx >> 7, h = idx & 127;
            float sum = 0.f;
            #pragma unroll
            for (int ww = 0; ww < 8; ww++)
                sum += smemf[OFF_H + (ww * TPS + tt) * HH + h];
            long g = (long)s * TPS + tt;
            if (g < NTILES)
                out[g * HH + h] = sum * (1.f / (float)CC);
        }
        __syncthreads();
    }

    if (w == 0) TC_DEALLOC(tb, TMEM_COLS);
#endif  // TC_OK
}

extern "C" void kernel_launch(void* const* d_in, const int* in_sizes, int n_in,
                              void* d_out, int out_size)
{
    const float* x  = (const float*)d_in[0];
    const float* A  = (const float*)d_in[1];
    const float* W0 = (const float*)d_in[2];
    const float* b0 = (const float*)d_in[3];
    const float* W1 = (const float*)d_in[4];
    const float* b1 = (const float*)d_in[5];
    float* out = (float*)d_out;

    cudaFuncSetAttribute(tgcn_tc_kernel, cudaFuncAttributeMaxDynamicSharedMemorySize, SMEM_BYTES);
    tgcn_tc_kernel<<<GRID, THREADS, SMEM_BYTES>>>(x, A, W0, b0, W1, b1, out);
}